// round 7
// baseline (speedup 1.0000x reference)
#include <cuda_runtime.h>
#include <math.h>

#define Bsz 256
#define Tt  500
#define Ii  128
#define Hh  512
#define CLIPV 5.0f

#define NBLK 128
#define NTHR 256
#define MT   16          // out columns per block (x3 gates)
#define BT   64          // batches per block
#define KCH  32          // staged k per chunk
#define NCH  10          // chunks per K-split (320 k each)
#define ASTR 66          // padded batch stride in staged tile
#define AST_BUF (KCH * ASTR)                   // float2 elements per buffer
#define SMEM_BYTES (2 * 2 * AST_BUF * 8)       // 2 splits x 2 bufs = 67584 B

typedef unsigned long long ull;

__device__ float    g_h[2][Bsz * Hh];
__device__ float4   g_wp[3 * 64 * 80 * 32];    // [gate][m8][kstep][lane]
__device__ unsigned g_cnt   = 0;
__device__ unsigned g_phase = 0;

__device__ __forceinline__ float tf32r(float v) {
    unsigned r;
    asm("cvt.rna.tf32.f32 %0, %1;" : "=r"(r) : "f"(v));
    return __uint_as_float(r);
}
__device__ __forceinline__ float sigf(float x) { return 1.f / (1.f + __expf(-x)); }

#define MMA_TF32(D, A0, A1, A2, A3, B0, B1)                              \
    asm volatile("mma.sync.aligned.m16n8k8.row.col.f32.tf32.tf32.f32 "   \
                 "{%0,%1,%2,%3},{%4,%5,%6,%7},{%8,%9},{%0,%1,%2,%3};"    \
                 : "+f"(D[0]), "+f"(D[1]), "+f"(D[2]), "+f"(D[3])        \
                 : "r"(A0), "r"(A1), "r"(A2), "r"(A3), "r"(B0), "r"(B1))

// One-time: split weights to tf32 hi/lo and pack in per-lane fragment order.
// b0 = W[n][k], b1 = W[n][k+4]; n = g*512 + m8*8 + (lane>>2); k = kstep*8 + (lane&3)
__global__ void pack_w(const float* __restrict__ w_ih, const float* __restrict__ w_hh) {
    int idx = blockIdx.x * blockDim.x + threadIdx.x;
    if (idx >= 3 * 64 * 80 * 32) return;
    int lane  = idx & 31;
    int kstep = (idx >> 5) % 80;
    int m8    = ((idx >> 5) / 80) % 64;
    int g     = (idx >> 5) / (80 * 64);
    int n = g * Hh + m8 * 8 + (lane >> 2);
    int k = kstep * 8 + (lane & 3);
    float v0, v1;
    if (k < Hh) { v0 = w_hh[n * Hh + k];      v1 = w_hh[n * Hh + k + 4]; }
    else        { v0 = w_ih[n * Ii + k - Hh]; v1 = w_ih[n * Ii + k - Hh + 4]; }
    float h0 = tf32r(v0), h1 = tf32r(v1);
    g_wp[idx] = make_float4(h0, tf32r(v0 - h0), h1, tf32r(v1 - h1));
}

// Persistent GRU: 128 blocks (32 m-tiles x 4 batch-tiles), 256 threads.
// 8 warps = 2 batch-groups x 2 out-halves x 2 K-splits.
// Warp tile: 32 batch (2 M-frags) x 24 out (3 gates x n8) x 320 K (40 k8 steps).
__global__ void __launch_bounds__(NTHR, 1) gru_persist(
    const float* __restrict__ x,      // (B, T, I)
    const float* __restrict__ h0,     // (B, H)
    const float* __restrict__ b_ih,   // (3H)
    const float* __restrict__ b_hh,   // (3H)
    float* __restrict__ out)          // (B, T, H) then (B, H) tail
{
    extern __shared__ char sm[];

    const int tid  = threadIdx.x;
    const int lane = tid & 31;
    const int w    = tid >> 5;
    const int bg   = w & 1;            // batch group (32 each)
    const int hf   = (w >> 1) & 1;     // out half (8 m each)
    const int ks   = w >> 2;           // K-split (320 k each)

    const int bm = blockIdx.x & 31;
    const int bt = blockIdx.x >> 5;
    const int m0 = bm * MT;
    const int b0 = bt * BT;
    const int m8blk = bm * 2 + hf;
    const int mcol  = m0 + hf * 8 + 2 * (lane & 3);   // this thread's m (and m+1)

    // staged A (h/x) for this split: [buf][klocal][batch] float2{hi,lo}
    float2* Asplit = (float2*)sm + ks * (2 * AST_BUF);
    const int colA = bg * 32 + (lane >> 2);

    // B fragment pointers (per gate), stride 32 float4 per kstep
    const float4* bp0 = g_wp + (((0 * 64 + m8blk) * 80 + ks * 40) * 32) + lane;
    const float4* bp1 = g_wp + (((1 * 64 + m8blk) * 80 + ks * 40) * 32) + lane;
    const float4* bp2 = g_wp + (((2 * 64 + m8blk) * 80 + ks * 40) * 32) + lane;

    unsigned bar_base = 0;
    if (tid == 0)
        asm volatile("ld.global.cg.u32 %0, [%1];" : "=r"(bar_base) : "l"(&g_phase));

    // biases for (mcol, mcol+1)
    const float2 cR  = make_float2(b_ih[mcol] + b_hh[mcol],
                                   b_ih[mcol + 1] + b_hh[mcol + 1]);
    const float2 cZ  = make_float2(b_ih[Hh + mcol] + b_hh[Hh + mcol],
                                   b_ih[Hh + mcol + 1] + b_hh[Hh + mcol + 1]);
    const float2 cNx = make_float2(b_ih[2 * Hh + mcol], b_ih[2 * Hh + mcol + 1]);
    const float2 cNh = make_float2(b_hh[2 * Hh + mcol], b_hh[2 * Hh + mcol + 1]);

    // staging mapping (128 threads per split)
    const int th = tid & 127;
    const int bA = th & 63;            // batch row
    const int kh = (th >> 6) * 16;     // k sub-range within 32-chunk

    float4 st_regs[4];

    for (int t = 0; t < Tt; t++) {
        const float* hsrc = (t == 0) ? h0 : g_h[t & 1];
        float*       hdst = g_h[(t + 1) & 1];

        __align__(16) float aR[2][4], aZ[2][4], aN[2][4], aNx[2][4];
        #pragma unroll
        for (int mf = 0; mf < 2; mf++)
            #pragma unroll
            for (int i = 0; i < 4; i++)
                { aR[mf][i] = 0.f; aZ[mf][i] = 0.f; aN[mf][i] = 0.f; aNx[mf][i] = 0.f; }

        auto ldgA = [&](int c) {
            const int kc = ks * 320 + c * KCH;
            const float* p = (kc < Hh)
                ? hsrc + (size_t)(b0 + bA) * Hh + kc + kh
                : x + ((size_t)(b0 + bA) * Tt + t) * Ii + (kc - Hh) + kh;
            #pragma unroll
            for (int j = 0; j < 4; j++)
                st_regs[j] = __ldcg((const float4*)(p + 4 * j));
        };
        auto stsA = [&](int buf) {
            float2* A = Asplit + buf * AST_BUF;
            #pragma unroll
            for (int j = 0; j < 4; j++) {
                const float vv[4] = {st_regs[j].x, st_regs[j].y, st_regs[j].z, st_regs[j].w};
                #pragma unroll
                for (int i = 0; i < 4; i++) {
                    const int kl = kh + 4 * j + i;
                    float hi = tf32r(vv[i]);
                    A[kl * ASTR + bA] = make_float2(hi, tf32r(vv[i] - hi));
                }
            }
        };

        float4 bb[3][3];               // B prefetch ring: [slot][gate]
        auto ldB = [&](int jq, int slot) {
            bb[slot][0] = bp0[jq * 32];
            bb[slot][1] = bp1[jq * 32];
            bb[slot][2] = bp2[jq * 32];
        };

        auto do_kstep = [&](int jj, const float2* Abuf, const float4* B, bool isH) {
            const int kb = jj * 8 + (lane & 3);
            const float2* r0 = Abuf + kb * ASTR + colA;
            const float2* r4 = Abuf + (kb + 4) * ASTR + colA;
            const unsigned bh[3][2] = {
                {__float_as_uint(B[0].x), __float_as_uint(B[0].z)},
                {__float_as_uint(B[1].x), __float_as_uint(B[1].z)},
                {__float_as_uint(B[2].x), __float_as_uint(B[2].z)}};
            const unsigned bl[3][2] = {
                {__float_as_uint(B[0].y), __float_as_uint(B[0].w)},
                {__float_as_uint(B[1].y), __float_as_uint(B[1].w)},
                {__float_as_uint(B[2].y), __float_as_uint(B[2].w)}};
            #pragma unroll
            for (int mf = 0; mf < 2; mf++) {
                float2 f0 = r0[mf * 16], f1 = r0[mf * 16 + 8];
                float2 f2 = r4[mf * 16], f3 = r4[mf * 16 + 8];
                unsigned ah0 = __float_as_uint(f0.x), ah1 = __float_as_uint(f1.x);
                unsigned ah2 = __float_as_uint(f2.x), ah3 = __float_as_uint(f3.x);
                unsigned al0 = __float_as_uint(f0.y), al1 = __float_as_uint(f1.y);
                unsigned al2 = __float_as_uint(f2.y), al3 = __float_as_uint(f3.y);
                float* aNs = isH ? aN[mf] : aNx[mf];
                MMA_TF32(aR[mf], ah0, ah1, ah2, ah3, bh[0][0], bh[0][1]);
                MMA_TF32(aZ[mf], ah0, ah1, ah2, ah3, bh[1][0], bh[1][1]);
                MMA_TF32(aNs,    ah0, ah1, ah2, ah3, bh[2][0], bh[2][1]);
                MMA_TF32(aR[mf], ah0, ah1, ah2, ah3, bl[0][0], bl[0][1]);
                MMA_TF32(aZ[mf], ah0, ah1, ah2, ah3, bl[1][0], bl[1][1]);
                MMA_TF32(aNs,    ah0, ah1, ah2, ah3, bl[2][0], bl[2][1]);
                MMA_TF32(aR[mf], al0, al1, al2, al3, bh[0][0], bh[0][1]);
                MMA_TF32(aZ[mf], al0, al1, al2, al3, bh[1][0], bh[1][1]);
                MMA_TF32(aNs,    al0, al1, al2, al3, bh[2][0], bh[2][1]);
            }
        };

        // ---- prologue: stage chunks 0,1; prefetch B ksteps 0..2 ----
        ldgA(0);
        stsA(0);
        ldgA(1);
        ldB(0, 0); ldB(1, 1); ldB(2, 2);
        asm volatile("bar.sync %0, 128;" :: "r"(ks + 1) : "memory");

        #pragma unroll 1
        for (int c = 0; c < NCH; c++) {
            const int buf = c & 1;
            if (c + 1 < NCH) stsA((c + 1) & 1);
            if (c + 2 < NCH) ldgA(c + 2);
            const float2* Abuf = Asplit + buf * AST_BUF;
            #pragma unroll
            for (int jj = 0; jj < 4; jj++) {
                const int j = c * 4 + jj;
                const bool isH = (ks == 0) || (j < 24);
                do_kstep(jj, Abuf, bb[j % 3], isH);
                if (j + 3 < 40) ldB(j + 3, j % 3);
            }
            asm volatile("bar.sync %0, 128;" :: "r"(ks + 1) : "memory");
        }

        // ---- K-split reduction (ks1 -> smem -> ks0) ----
        __syncthreads();
        float4* R = (float4*)sm;
        const int ridx = ((w & 3) * 32 + lane) * 8;
        if (ks == 1) {
            R[ridx + 0] = *(float4*)aR[0];  R[ridx + 1] = *(float4*)aR[1];
            R[ridx + 2] = *(float4*)aZ[0];  R[ridx + 3] = *(float4*)aZ[1];
            R[ridx + 4] = *(float4*)aN[0];  R[ridx + 5] = *(float4*)aN[1];
            R[ridx + 6] = *(float4*)aNx[0]; R[ridx + 7] = *(float4*)aNx[1];
        }
        __syncthreads();

        if (ks == 0) {
            auto addf4 = [](float* a, float4 v) {
                a[0] += v.x; a[1] += v.y; a[2] += v.z; a[3] += v.w;
            };
            addf4(aR[0],  R[ridx + 0]); addf4(aR[1],  R[ridx + 1]);
            addf4(aZ[0],  R[ridx + 2]); addf4(aZ[1],  R[ridx + 3]);
            addf4(aN[0],  R[ridx + 4]); addf4(aN[1],  R[ridx + 5]);
            addf4(aNx[0], R[ridx + 6]); addf4(aNx[1], R[ridx + 7]);

            // ---- gates epilogue: 2 M-frags x 2 row-halves x 2 cols ----
            #pragma unroll
            for (int mf = 0; mf < 2; mf++) {
                #pragma unroll
                for (int rh = 0; rh < 2; rh++) {
                    const int b = b0 + bg * 32 + mf * 16 + (lane >> 2) + rh * 8;
                    const int i0 = rh * 2;
                    float2 hp = __ldcg((const float2*)(hsrc + (size_t)b * Hh + mcol));

                    float rl = sigf(aR[mf][i0]     + cR.x);
                    float rr = sigf(aR[mf][i0 + 1] + cR.y);
                    float zl = sigf(aZ[mf][i0]     + cZ.x);
                    float zr = sigf(aZ[mf][i0 + 1] + cZ.y);
                    float nl = tanhf(aNx[mf][i0]     + cNx.x + rl * (aN[mf][i0]     + cNh.x));
                    float nr = tanhf(aNx[mf][i0 + 1] + cNx.y + rr * (aN[mf][i0 + 1] + cNh.y));

                    float hl = (1.f - zl) * nl + zl * hp.x;
                    float hr = (1.f - zr) * nr + zr * hp.y;
                    hl = fminf(fmaxf(hl, -CLIPV), CLIPV);
                    hr = fminf(fmaxf(hr, -CLIPV), CLIPV);

                    float2 res = make_float2(hl, hr);
                    __stcg((float2*)(hdst + (size_t)b * Hh + mcol), res);
                    *(float2*)(out + ((size_t)b * Tt + t) * Hh + mcol) = res;
                    if (t == Tt - 1)
                        *(float2*)(out + (size_t)Bsz * Tt * Hh + (size_t)b * Hh + mcol) = res;
                }
            }
        }

        // ---- grid barrier (monotonic phase, wrap-safe) ----
        __syncthreads();
        if (tid == 0) {
            __threadfence();
            unsigned old = atomicAdd(&g_cnt, 1u);
            if (old == (unsigned)(NBLK - 1)) {
                atomicExch(&g_cnt, 0u);
                __threadfence();
                atomicAdd(&g_phase, 1u);
            } else {
                const unsigned tgt = bar_base + (unsigned)(t + 1);
                unsigned v;
                do {
                    __nanosleep(32);
                    asm volatile("ld.global.cg.u32 %0, [%1];" : "=r"(v) : "l"(&g_phase));
                } while ((int)(v - tgt) < 0);
            }
            __threadfence();
        }
        __syncthreads();
    }
}

extern "C" void kernel_launch(void* const* d_in, const int* in_sizes, int n_in,
                              void* d_out, int out_size)
{
    (void)in_sizes; (void)n_in; (void)out_size;
    const float* x    = (const float*)d_in[0];
    const float* h0   = (const float*)d_in[1];
    const float* w_ih = (const float*)d_in[2];
    const float* w_hh = (const float*)d_in[3];
    const float* b_ih = (const float*)d_in[4];
    const float* b_hh = (const float*)d_in[5];
    float* out = (float*)d_out;

    cudaFuncSetAttribute(gru_persist, cudaFuncAttributeMaxDynamicSharedMemorySize,
                         SMEM_BYTES);

    pack_w<<<(3 * 64 * 80 * 32 + 255) / 256, 256>>>(w_ih, w_hh);
    gru_persist<<<NBLK, NTHR, SMEM_BYTES>>>(x, h0, b_ih, b_hh, out);
}